// round 1
// baseline (speedup 1.0000x reference)
#include <cuda_runtime.h>
#include <cstddef>

#define NN   50000      // nodes
#define NE   800000     // edges
#define DD   128        // feature dim (in/hidden)
#define KK   256        // concat dim = 2*DD

// ---------------- device scratch (static; no allocs allowed) ----------------
__device__ int   g_cnt[NN];        // histogram, then CSR cursor
__device__ int   g_off[NN + 1];    // CSR offsets
__device__ int   g_col[NE];        // CSR: source node per edge slot
__device__ float g_wgt[NE];        // CSR: edge weight per edge slot
__device__ float g_deg[NN];        // weighted degree
__device__ float g_agg[NN * DD];   // normalized aggregation (agg/deg)
__device__ float g_h0[NN * DD];    // hidden layer 0 output
__device__ float g_h1[NN * DD];    // hidden layer 1 output

// ---------------- CSR build ----------------
__global__ void count_kernel(const int* __restrict__ ei, const float* __restrict__ ew) {
    int e = blockIdx.x * blockDim.x + threadIdx.x;
    if (e >= NE) return;
    int r = ei[e];                 // dst
    atomicAdd(&g_cnt[r], 1);
    atomicAdd(&g_deg[r], ew[e]);
}

__global__ void scan_kernel() {
    __shared__ int warp_sums[32];
    __shared__ int s_total;
    __shared__ int s_base;
    const int tid = threadIdx.x, lane = tid & 31, wid = tid >> 5;
    if (tid == 0) s_base = 0;
    __syncthreads();
    for (int start = 0; start < NN; start += 1024) {
        int i = start + tid;
        int v = (i < NN) ? g_cnt[i] : 0;
        // warp inclusive scan
        int incl = v;
        #pragma unroll
        for (int o = 1; o < 32; o <<= 1) {
            int t = __shfl_up_sync(0xffffffffu, incl, o);
            if (lane >= o) incl += t;
        }
        if (lane == 31) warp_sums[wid] = incl;
        __syncthreads();
        if (wid == 0) {
            int wv = warp_sums[lane];
            int ws = wv;
            #pragma unroll
            for (int o = 1; o < 32; o <<= 1) {
                int t = __shfl_up_sync(0xffffffffu, ws, o);
                if (lane >= o) ws += t;
            }
            if (lane == 31) s_total = ws;
            warp_sums[lane] = ws - wv;     // exclusive warp offsets
        }
        __syncthreads();
        int excl = incl - v + warp_sums[wid];
        int o = s_base + excl;
        if (i < NN) { g_off[i] = o; g_cnt[i] = o; }   // cursor init = offset
        __syncthreads();
        if (tid == 0) s_base += s_total;
        __syncthreads();
    }
    if (tid == 0) g_off[NN] = s_base;    // == NE
}

__global__ void fill_kernel(const int* __restrict__ ei, const float* __restrict__ ew) {
    int e = blockIdx.x * blockDim.x + threadIdx.x;
    if (e >= NE) return;
    int r = ei[e];
    int c = ei[NE + e];
    float w = ew[e];
    int pos = atomicAdd(&g_cnt[r], 1);
    g_col[pos] = c;
    g_wgt[pos] = w;
}

// ---------------- aggregation: warp per node, CSR gather ----------------
__global__ void agg_kernel(const float* __restrict__ xin) {
    int gw = (blockIdx.x * blockDim.x + threadIdx.x) >> 5;  // node id
    if (gw >= NN) return;
    const int lane = threadIdx.x & 31;
    const int s = g_off[gw];
    const int e = g_off[gw + 1];
    float4 acc = make_float4(0.f, 0.f, 0.f, 0.f);
    for (int base = s; base < e; base += 32) {
        int nn = min(32, e - base);
        int c = 0; float w = 0.f;
        if (lane < nn) { c = g_col[base + lane]; w = g_wgt[base + lane]; }
        for (int j = 0; j < nn; ++j) {
            int cj = __shfl_sync(0xffffffffu, c, j);
            float wj = __shfl_sync(0xffffffffu, w, j);
            float4 v = *(const float4*)(xin + (size_t)cj * DD + lane * 4);
            acc.x = fmaf(v.x, wj, acc.x);
            acc.y = fmaf(v.y, wj, acc.y);
            acc.z = fmaf(v.z, wj, acc.z);
            acc.w = fmaf(v.w, wj, acc.w);
        }
    }
    float invd = 1.0f / fmaxf(g_deg[gw], 1.0f);
    float4* o = (float4*)(g_agg + (size_t)gw * DD);
    o[lane] = make_float4(acc.x * invd, acc.y * invd, acc.z * invd, acc.w * invd);
}

// ---------------- fused GEMM: out = [xin | agg] @ W^T + b (+relu) ----------------
// BM=128, BK=16, K total = 256 (first 128 from xin, next 128 from g_agg).
// 256 threads: tx = tid%16 (TN cols each), ty = tid/16 (8 rows each).
template <int BN, int TN, bool RELU>
__global__ void __launch_bounds__(256) gemm_kernel(
    const float* __restrict__ xin,
    const float* __restrict__ W,     // [BN, 256] row-major
    const float* __restrict__ bias,  // [BN]
    float* __restrict__ out)         // [NN, BN]
{
    __shared__ float As[16][128];
    __shared__ float Bs[16][BN];

    const int tid = threadIdx.x;
    const int tx = tid & 15;
    const int ty = tid >> 4;
    const int m0 = blockIdx.x * 128;

    float acc[8][TN];
    #pragma unroll
    for (int i = 0; i < 8; ++i)
        #pragma unroll
        for (int j = 0; j < TN; ++j) acc[i][j] = 0.f;

    #pragma unroll 1
    for (int kt = 0; kt < 16; ++kt) {
        const int kg = kt * 16;                       // global k column 0..255
        const float* Asrc = (kt < 8) ? (xin + kg) : (g_agg + (kg - 128));
        // load A tile [128 rows x 16 k] -> transposed As[k][m]
        #pragma unroll
        for (int it = 0; it < 2; ++it) {
            int idx = tid * 2 + it;                   // 0..511 float4 slots
            int row = idx >> 2;
            int cf = idx & 3;
            float4 v = make_float4(0.f, 0.f, 0.f, 0.f);
            int gr = m0 + row;
            if (gr < NN) v = *(const float4*)(Asrc + (size_t)gr * DD + cf * 4);
            As[cf * 4 + 0][row] = v.x;
            As[cf * 4 + 1][row] = v.y;
            As[cf * 4 + 2][row] = v.z;
            As[cf * 4 + 3][row] = v.w;
        }
        // load B tile [BN rows x 16 k] -> transposed Bs[k][n]
        #pragma unroll
        for (int idx = tid; idx < (BN * 16) / 4; idx += 256) {
            int n = idx >> 2;
            int cf = idx & 3;
            float4 v = *(const float4*)(W + (size_t)n * KK + kg + cf * 4);
            Bs[cf * 4 + 0][n] = v.x;
            Bs[cf * 4 + 1][n] = v.y;
            Bs[cf * 4 + 2][n] = v.z;
            Bs[cf * 4 + 3][n] = v.w;
        }
        __syncthreads();
        #pragma unroll
        for (int k = 0; k < 16; ++k) {
            float a[8], b[TN];
            #pragma unroll
            for (int i = 0; i < 8; ++i) a[i] = As[k][ty * 8 + i];
            #pragma unroll
            for (int j = 0; j < TN; ++j) b[j] = Bs[k][tx * TN + j];
            #pragma unroll
            for (int i = 0; i < 8; ++i)
                #pragma unroll
                for (int j = 0; j < TN; ++j)
                    acc[i][j] = fmaf(a[i], b[j], acc[i][j]);
        }
        __syncthreads();
    }

    float bv[TN];
    #pragma unroll
    for (int j = 0; j < TN; ++j) bv[j] = __ldg(&bias[tx * TN + j]);

    #pragma unroll
    for (int i = 0; i < 8; ++i) {
        int r = m0 + ty * 8 + i;
        if (r < NN) {
            #pragma unroll
            for (int j = 0; j < TN; ++j) {
                float v = acc[i][j] + bv[j];
                if (RELU) v = fmaxf(v, 0.f);
                out[(size_t)r * BN + tx * TN + j] = v;
            }
        }
    }
}

// ---------------- launch ----------------
extern "C" void kernel_launch(void* const* d_in, const int* in_sizes, int n_in,
                              void* d_out, int out_size) {
    (void)in_sizes; (void)n_in; (void)out_size;
    const float* x  = (const float*)d_in[0];
    const int*   ei = (const int*)d_in[1];
    const float* ew = (const float*)d_in[2];
    const float* W0 = (const float*)d_in[3];
    const float* b0 = (const float*)d_in[4];
    const float* W1 = (const float*)d_in[5];
    const float* b1 = (const float*)d_in[6];
    const float* W2 = (const float*)d_in[7];
    const float* b2 = (const float*)d_in[8];
    float* out = (float*)d_out;

    void *p_cnt, *p_deg, *p_h0, *p_h1;
    cudaGetSymbolAddress(&p_cnt, g_cnt);
    cudaGetSymbolAddress(&p_deg, g_deg);
    cudaGetSymbolAddress(&p_h0,  g_h0);
    cudaGetSymbolAddress(&p_h1,  g_h1);
    float* h0 = (float*)p_h0;
    float* h1 = (float*)p_h1;

    cudaMemsetAsync(p_cnt, 0, NN * sizeof(int), 0);
    cudaMemsetAsync(p_deg, 0, NN * sizeof(float), 0);

    count_kernel<<<(NE + 255) / 256, 256>>>(ei, ew);
    scan_kernel<<<1, 1024>>>();
    fill_kernel<<<(NE + 255) / 256, 256>>>(ei, ew);

    const int aggBlocks  = (NN + 7) / 8;          // 8 warps/block of 256
    const int gemmBlocks = (NN + 127) / 128;

    // layer 0: h0 = relu([x | agg(x)] @ W0^T + b0)
    agg_kernel<<<aggBlocks, 256>>>(x);
    gemm_kernel<128, 8, true><<<gemmBlocks, 256>>>(x, W0, b0, h0);

    // layer 1: h1 = relu([h0 | agg(h0)] @ W1^T + b1)
    agg_kernel<<<aggBlocks, 256>>>(h0);
    gemm_kernel<128, 8, true><<<gemmBlocks, 256>>>(h0, W1, b1, h1);

    // layer 2: out = [h1 | agg(h1)] @ W2^T + b2
    agg_kernel<<<aggBlocks, 256>>>(h1);
    gemm_kernel<64, 4, false><<<gemmBlocks, 256>>>(h1, W2, b2, out);
}

// round 2
// speedup vs baseline: 1.1718x; 1.1718x over previous
#include <cuda_runtime.h>
#include <cstddef>

#define NN   50000      // nodes
#define NE   800000     // edges
#define DD   128        // feature dim (in/hidden)
#define KK   256        // concat dim = 2*DD

typedef unsigned long long ull;

// ---------------- packed f32x2 helpers ----------------
__device__ __forceinline__ ull pack2(float x, float y) {
    ull r; asm("mov.b64 %0, {%1, %2};" : "=l"(r) : "f"(x), "f"(y)); return r;
}
__device__ __forceinline__ float2 unpack2(ull v) {
    float2 r; asm("mov.b64 {%0, %1}, %2;" : "=f"(r.x), "=f"(r.y) : "l"(v)); return r;
}
__device__ __forceinline__ void fma2(ull& d, ull a, ull b) {
    asm("fma.rn.f32x2 %0, %1, %2, %0;" : "+l"(d) : "l"(a), "l"(b));
}

// ---------------- device scratch (static; no allocs allowed) ----------------
__device__ int   g_cnt[NN];        // histogram, then CSR cursor
__device__ int   g_off[NN + 1];    // CSR offsets
__device__ int   g_col[NE];        // CSR: source node per edge slot
__device__ float g_wgt[NE];        // CSR: edge weight per edge slot
__device__ float g_deg[NN];        // weighted degree
__device__ float g_agg[NN * DD];   // normalized aggregation (agg/deg)
__device__ float g_h0[NN * DD];    // hidden layer 0 output
__device__ float g_h1[NN * DD];    // hidden layer 1 output

// ---------------- CSR build ----------------
__global__ void count_kernel(const int* __restrict__ ei, const float* __restrict__ ew) {
    int e = blockIdx.x * blockDim.x + threadIdx.x;
    if (e >= NE) return;
    int r = ei[e];                 // dst
    atomicAdd(&g_cnt[r], 1);
    atomicAdd(&g_deg[r], ew[e]);
}

__global__ void scan_kernel() {
    __shared__ int warp_sums[32];
    __shared__ int s_total;
    __shared__ int s_base;
    const int tid = threadIdx.x, lane = tid & 31, wid = tid >> 5;
    if (tid == 0) s_base = 0;
    __syncthreads();
    for (int start = 0; start < NN; start += 1024) {
        int i = start + tid;
        int v = (i < NN) ? g_cnt[i] : 0;
        int incl = v;
        #pragma unroll
        for (int o = 1; o < 32; o <<= 1) {
            int t = __shfl_up_sync(0xffffffffu, incl, o);
            if (lane >= o) incl += t;
        }
        if (lane == 31) warp_sums[wid] = incl;
        __syncthreads();
        if (wid == 0) {
            int wv = warp_sums[lane];
            int ws = wv;
            #pragma unroll
            for (int o = 1; o < 32; o <<= 1) {
                int t = __shfl_up_sync(0xffffffffu, ws, o);
                if (lane >= o) ws += t;
            }
            if (lane == 31) s_total = ws;
            warp_sums[lane] = ws - wv;     // exclusive warp offsets
        }
        __syncthreads();
        int excl = incl - v + warp_sums[wid];
        int o = s_base + excl;
        if (i < NN) { g_off[i] = o; g_cnt[i] = o; }   // cursor init = offset
        __syncthreads();
        if (tid == 0) s_base += s_total;
        __syncthreads();
    }
    if (tid == 0) g_off[NN] = s_base;    // == NE
}

__global__ void fill_kernel(const int* __restrict__ ei, const float* __restrict__ ew) {
    int e = blockIdx.x * blockDim.x + threadIdx.x;
    if (e >= NE) return;
    int r = ei[e];
    int c = ei[NE + e];
    float w = ew[e];
    int pos = atomicAdd(&g_cnt[r], 1);
    g_col[pos] = c;
    g_wgt[pos] = w;
}

// ---------------- aggregation: warp per node, CSR gather ----------------
__global__ void agg_kernel(const float* __restrict__ xin) {
    int gw = (blockIdx.x * blockDim.x + threadIdx.x) >> 5;  // node id
    if (gw >= NN) return;
    const int lane = threadIdx.x & 31;
    const int s = g_off[gw];
    const int e = g_off[gw + 1];
    float4 acc = make_float4(0.f, 0.f, 0.f, 0.f);
    for (int base = s; base < e; base += 32) {
        int nn = min(32, e - base);
        int c = 0; float w = 0.f;
        if (lane < nn) { c = g_col[base + lane]; w = g_wgt[base + lane]; }
        for (int j = 0; j < nn; ++j) {
            int cj = __shfl_sync(0xffffffffu, c, j);
            float wj = __shfl_sync(0xffffffffu, w, j);
            float4 v = *(const float4*)(xin + (size_t)cj * DD + lane * 4);
            acc.x = fmaf(v.x, wj, acc.x);
            acc.y = fmaf(v.y, wj, acc.y);
            acc.z = fmaf(v.z, wj, acc.z);
            acc.w = fmaf(v.w, wj, acc.w);
        }
    }
    float invd = 1.0f / fmaxf(g_deg[gw], 1.0f);
    float4* o = (float4*)(g_agg + (size_t)gw * DD);
    o[lane] = make_float4(acc.x * invd, acc.y * invd, acc.z * invd, acc.w * invd);
}

// ---------------- fused GEMM: out = [xin | agg] @ W^T + b (+relu) ----------------
// BM=128, BK=16, K total = 256 (first 128 from xin, next 128 from g_agg).
// 256 threads: tx = tid%16, ty = tid/16 (8 rows each).
// Per-thread N columns: two groups of G=TN/2 floats at cols tx*G and BN/2+tx*G.
// Group loads are LDS.128/LDS.64, conflict-free. FMA via packed fma.rn.f32x2.
template <int BN, int TN, bool RELU>
__global__ void __launch_bounds__(256, 2) gemm_kernel(
    const float* __restrict__ xin,
    const float* __restrict__ W,     // [BN, 256] row-major
    const float* __restrict__ bias,  // [BN]
    float* __restrict__ out)         // [NN, BN]
{
    __shared__ float As[16][128];
    __shared__ float Bs[16][BN];

    constexpr int G  = TN / 2;   // floats per group (4 or 2)
    constexpr int NP = G / 2;    // f32x2 pairs per group (2 or 1)

    const int tid = threadIdx.x;
    const int tx = tid & 15;
    const int ty = tid >> 4;
    const int m0 = blockIdx.x * 128;

    ull acc[8][2][NP];
    #pragma unroll
    for (int i = 0; i < 8; ++i)
        #pragma unroll
        for (int g = 0; g < 2; ++g)
            #pragma unroll
            for (int p = 0; p < NP; ++p) acc[i][g][p] = 0ULL;

    #pragma unroll 1
    for (int kt = 0; kt < 16; ++kt) {
        const int kg = kt * 16;                       // global k column 0..255
        const float* Asrc = (kt < 8) ? (xin + kg) : (g_agg + (kg - 128));
        // load A tile [128 rows x 16 k] -> transposed As[k][m]
        #pragma unroll
        for (int it = 0; it < 2; ++it) {
            int idx = tid * 2 + it;                   // 0..511 float4 slots
            int row = idx >> 2;
            int cf = idx & 3;
            float4 v = make_float4(0.f, 0.f, 0.f, 0.f);
            int gr = m0 + row;
            if (gr < NN) v = *(const float4*)(Asrc + (size_t)gr * DD + cf * 4);
            As[cf * 4 + 0][row] = v.x;
            As[cf * 4 + 1][row] = v.y;
            As[cf * 4 + 2][row] = v.z;
            As[cf * 4 + 3][row] = v.w;
        }
        // load B tile [BN rows x 16 k] -> transposed Bs[k][n]
        #pragma unroll
        for (int idx = tid; idx < (BN * 16) / 4; idx += 256) {
            int n = idx >> 2;
            int cf = idx & 3;
            float4 v = *(const float4*)(W + (size_t)n * KK + kg + cf * 4);
            Bs[cf * 4 + 0][n] = v.x;
            Bs[cf * 4 + 1][n] = v.y;
            Bs[cf * 4 + 2][n] = v.z;
            Bs[cf * 4 + 3][n] = v.w;
        }
        __syncthreads();
        #pragma unroll
        for (int k = 0; k < 16; ++k) {
            // a: 8 rows, vector loads (broadcast across tx -> conflict-free)
            float4 a0 = *(const float4*)&As[k][ty * 8];
            float4 a1 = *(const float4*)&As[k][ty * 8 + 4];
            float a[8] = {a0.x, a0.y, a0.z, a0.w, a1.x, a1.y, a1.z, a1.w};
            ull a2[8];
            #pragma unroll
            for (int i = 0; i < 8; ++i) a2[i] = pack2(a[i], a[i]);
            // b: two groups, vector loads (stride-G -> conflict-free phases)
            ull b2[2][NP];
            #pragma unroll
            for (int g = 0; g < 2; ++g) {
                const float2* bp = (const float2*)&Bs[k][g * (BN / 2) + tx * G];
                #pragma unroll
                for (int p = 0; p < NP; ++p) {
                    float2 t = bp[p];
                    b2[g][p] = pack2(t.x, t.y);
                }
            }
            #pragma unroll
            for (int i = 0; i < 8; ++i)
                #pragma unroll
                for (int g = 0; g < 2; ++g)
                    #pragma unroll
                    for (int p = 0; p < NP; ++p)
                        fma2(acc[i][g][p], a2[i], b2[g][p]);
        }
        __syncthreads();
    }

    // bias (per-group pairs)
    float2 bv[2][NP];
    #pragma unroll
    for (int g = 0; g < 2; ++g)
        #pragma unroll
        for (int p = 0; p < NP; ++p) {
            int c = g * (BN / 2) + tx * G + p * 2;
            bv[g][p] = make_float2(__ldg(&bias[c]), __ldg(&bias[c + 1]));
        }

    #pragma unroll
    for (int i = 0; i < 8; ++i) {
        int r = m0 + ty * 8 + i;
        if (r < NN) {
            #pragma unroll
            for (int g = 0; g < 2; ++g) {
                float vals[G];
                #pragma unroll
                for (int p = 0; p < NP; ++p) {
                    float2 t = unpack2(acc[i][g][p]);
                    float v0 = t.x + bv[g][p].x;
                    float v1 = t.y + bv[g][p].y;
                    if (RELU) { v0 = fmaxf(v0, 0.f); v1 = fmaxf(v1, 0.f); }
                    vals[p * 2] = v0; vals[p * 2 + 1] = v1;
                }
                float* op = out + (size_t)r * BN + g * (BN / 2) + tx * G;
                if (G == 4) {
                    *(float4*)op = make_float4(vals[0], vals[1], vals[G > 2 ? 2 : 0], vals[G > 2 ? 3 : 1]);
                } else {
                    *(float2*)op = make_float2(vals[0], vals[1]);
                }
            }
        }
    }
}

// ---------------- launch ----------------
extern "C" void kernel_launch(void* const* d_in, const int* in_sizes, int n_in,
                              void* d_out, int out_size) {
    (void)in_sizes; (void)n_in; (void)out_size;
    const float* x  = (const float*)d_in[0];
    const int*   ei = (const int*)d_in[1];
    const float* ew = (const float*)d_in[2];
    const float* W0 = (const float*)d_in[3];
    const float* b0 = (const float*)d_in[4];
    const float* W1 = (const float*)d_in[5];
    const float* b1 = (const float*)d_in[6];
    const float* W2 = (const float*)d_in[7];
    const float* b2 = (const float*)d_in[8];
    float* out = (float*)d_out;

    void *p_cnt, *p_deg, *p_h0, *p_h1;
    cudaGetSymbolAddress(&p_cnt, g_cnt);
    cudaGetSymbolAddress(&p_deg, g_deg);
    cudaGetSymbolAddress(&p_h0,  g_h0);
    cudaGetSymbolAddress(&p_h1,  g_h1);
    float* h0 = (float*)p_h0;
    float* h1 = (float*)p_h1;

    cudaMemsetAsync(p_cnt, 0, NN * sizeof(int), 0);
    cudaMemsetAsync(p_deg, 0, NN * sizeof(float), 0);

    count_kernel<<<(NE + 255) / 256, 256>>>(ei, ew);
    scan_kernel<<<1, 1024>>>();
    fill_kernel<<<(NE + 255) / 256, 256>>>(ei, ew);

    const int aggBlocks  = (NN + 7) / 8;          // 8 warps/block of 256
    const int gemmBlocks = (NN + 127) / 128;

    // layer 0: h0 = relu([x | agg(x)] @ W0^T + b0)
    agg_kernel<<<aggBlocks, 256>>>(x);
    gemm_kernel<128, 8, true><<<gemmBlocks, 256>>>(x, W0, b0, h0);

    // layer 1: h1 = relu([h0 | agg(h0)] @ W1^T + b1)
    agg_kernel<<<aggBlocks, 256>>>(h0);
    gemm_kernel<128, 8, true><<<gemmBlocks, 256>>>(h0, W1, b1, h1);

    // layer 2: out = [h1 | agg(h1)] @ W2^T + b2
    agg_kernel<<<aggBlocks, 256>>>(h1);
    gemm_kernel<64, 4, false><<<gemmBlocks, 256>>>(h1, W2, b2, out);
}

// round 3
// speedup vs baseline: 1.2049x; 1.0283x over previous
#include <cuda_runtime.h>
#include <cstddef>

#define NN   50000      // nodes
#define NE   800000     // edges
#define DD   128        // feature dim (in/hidden)
#define KK   256        // concat dim = 2*DD

typedef unsigned long long ull;

// ---------------- packed f32x2 helpers ----------------
__device__ __forceinline__ ull pack2(float x, float y) {
    ull r; asm("mov.b64 %0, {%1, %2};" : "=l"(r) : "f"(x), "f"(y)); return r;
}
__device__ __forceinline__ float2 unpack2(ull v) {
    float2 r; asm("mov.b64 {%0, %1}, %2;" : "=f"(r.x), "=f"(r.y) : "l"(v)); return r;
}
__device__ __forceinline__ void fma2(ull& d, ull a, ull b) {
    asm("fma.rn.f32x2 %0, %1, %2, %0;" : "+l"(d) : "l"(a), "l"(b));
}

// ---------------- device scratch (static; no allocs allowed) ----------------
__device__ int   g_cnt[NN];        // histogram, then CSR cursor
__device__ int   g_off[NN + 1];    // CSR offsets
__device__ int   g_col[NE];        // CSR: source node per edge slot
__device__ float g_wgt[NE];        // CSR: edge weight per edge slot
__device__ float g_deg[NN];        // weighted degree
__device__ float g_agg[NN * DD];   // normalized aggregation (agg/deg)
__device__ float g_h0[NN * DD];    // hidden layer 0 output
__device__ float g_h1[NN * DD];    // hidden layer 1 output
__device__ float g_Wt0[KK * 128];  // W0^T : [256][128]
__device__ float g_Wt1[KK * 128];  // W1^T : [256][128]
__device__ float g_Wt2[KK * 64];   // W2^T : [256][64]

// ---------------- weight transpose: Wt[k][n] = W[n][k] ----------------
__global__ void transpose_W(const float* __restrict__ W0,
                            const float* __restrict__ W1,
                            const float* __restrict__ W2) {
    int i = blockIdx.x * 256 + threadIdx.x;
    if (i < KK * 128) {
        g_Wt0[i] = W0[(i % 128) * KK + i / 128];
    } else if (i < 2 * KK * 128) {
        int j = i - KK * 128;
        g_Wt1[j] = W1[(j % 128) * KK + j / 128];
    } else if (i < 2 * KK * 128 + KK * 64) {
        int j = i - 2 * KK * 128;
        g_Wt2[j] = W2[(j % 64) * KK + j / 64];
    }
}

// ---------------- CSR build ----------------
__global__ void count_kernel(const int* __restrict__ ei, const float* __restrict__ ew) {
    int e = blockIdx.x * blockDim.x + threadIdx.x;
    if (e >= NE) return;
    int r = ei[e];                 // dst
    atomicAdd(&g_cnt[r], 1);
    atomicAdd(&g_deg[r], ew[e]);
}

// vectorized single-block scan: 1024 threads x 4 elems = 4096/round
__global__ void scan_kernel() {
    __shared__ int warp_sums[32];
    __shared__ int s_total;
    __shared__ int s_base;
    const int tid = threadIdx.x, lane = tid & 31, wid = tid >> 5;
    if (tid == 0) s_base = 0;
    __syncthreads();
    for (int start = 0; start < NN; start += 4096) {
        int i0 = start + tid * 4;
        int v[4];
        #pragma unroll
        for (int j = 0; j < 4; ++j) v[j] = (i0 + j < NN) ? g_cnt[i0 + j] : 0;
        int tsum = v[0] + v[1] + v[2] + v[3];
        int incl = tsum;
        #pragma unroll
        for (int o = 1; o < 32; o <<= 1) {
            int t = __shfl_up_sync(0xffffffffu, incl, o);
            if (lane >= o) incl += t;
        }
        if (lane == 31) warp_sums[wid] = incl;
        __syncthreads();
        if (wid == 0) {
            int wv = warp_sums[lane];
            int ws = wv;
            #pragma unroll
            for (int o = 1; o < 32; o <<= 1) {
                int t = __shfl_up_sync(0xffffffffu, ws, o);
                if (lane >= o) ws += t;
            }
            if (lane == 31) s_total = ws;
            warp_sums[lane] = ws - wv;     // exclusive warp offsets
        }
        __syncthreads();
        int run = s_base + incl - tsum + warp_sums[wid];
        #pragma unroll
        for (int j = 0; j < 4; ++j) {
            if (i0 + j < NN) { g_off[i0 + j] = run; g_cnt[i0 + j] = run; run += v[j]; }
        }
        __syncthreads();
        if (tid == 0) s_base += s_total;
        __syncthreads();
    }
    if (tid == 0) g_off[NN] = s_base;    // == NE
}

__global__ void fill_kernel(const int* __restrict__ ei, const float* __restrict__ ew) {
    int e = blockIdx.x * blockDim.x + threadIdx.x;
    if (e >= NE) return;
    int r = ei[e];
    int c = ei[NE + e];
    float w = ew[e];
    int pos = atomicAdd(&g_cnt[r], 1);
    g_col[pos] = c;
    g_wgt[pos] = w;
}

// ---------------- aggregation: warp per node, CSR gather ----------------
__global__ void agg_kernel(const float* __restrict__ xin) {
    int gw = (blockIdx.x * blockDim.x + threadIdx.x) >> 5;  // node id
    if (gw >= NN) return;
    const int lane = threadIdx.x & 31;
    const int s = g_off[gw];
    const int e = g_off[gw + 1];
    float4 acc = make_float4(0.f, 0.f, 0.f, 0.f);
    for (int base = s; base < e; base += 32) {
        int nn = min(32, e - base);
        int c = 0; float w = 0.f;
        if (lane < nn) { c = g_col[base + lane]; w = g_wgt[base + lane]; }
        for (int j = 0; j < nn; ++j) {
            int cj = __shfl_sync(0xffffffffu, c, j);
            float wj = __shfl_sync(0xffffffffu, w, j);
            float4 v = *(const float4*)(xin + (size_t)cj * DD + lane * 4);
            acc.x = fmaf(v.x, wj, acc.x);
            acc.y = fmaf(v.y, wj, acc.y);
            acc.z = fmaf(v.z, wj, acc.z);
            acc.w = fmaf(v.w, wj, acc.w);
        }
    }
    float invd = 1.0f / fmaxf(g_deg[gw], 1.0f);
    float4* o = (float4*)(g_agg + (size_t)gw * DD);
    o[lane] = make_float4(acc.x * invd, acc.y * invd, acc.z * invd, acc.w * invd);
}

// ---------------- fused GEMM (double-buffered): out = [xin | agg] @ W^T + b ----
// BM=128, BK=16, K=256 (first 128 cols from xin, next 128 from g_agg).
// B read from pre-transposed Wt[256][BN] -> linear smem copy (no transpose STS).
// 256 threads: tx = tid%16, ty = tid/16 (8 rows each).
// Per-thread N cols: two groups of G=TN/2 at cols tx*G and BN/2+tx*G.
// FMA via packed fma.rn.f32x2.
template <int BN, int TN, bool RELU>
__global__ void __launch_bounds__(256, 2) gemm_kernel(
    const float* __restrict__ xin,
    const float* __restrict__ Wt,    // [256][BN]
    const float* __restrict__ bias,  // [BN]
    float* __restrict__ out)         // [NN, BN]
{
    __shared__ float As[2][16][128];
    __shared__ float Bs[2][16][BN];

    constexpr int G   = TN / 2;         // floats per group (4 or 2)
    constexpr int NP  = G / 2;          // f32x2 pairs per group (2 or 1)
    constexpr int BLD = (BN * 16) / (4 * 256);  // B float4 per thread (2 or 1)

    const int tid = threadIdx.x;
    const int tx = tid & 15;
    const int ty = tid >> 4;
    const int m0 = blockIdx.x * 128;

    ull acc[8][2][NP];
    #pragma unroll
    for (int i = 0; i < 8; ++i)
        #pragma unroll
        for (int g = 0; g < 2; ++g)
            #pragma unroll
            for (int p = 0; p < NP; ++p) acc[i][g][p] = 0ULL;

    float4 stA[2], stB[BLD];

    // --- staging loads ---
    auto loadT = [&](int kt) {
        const int kg = kt * 16;
        const float* Asrc = (kt < 8) ? (xin + kg) : (g_agg + (kg - 128));
        #pragma unroll
        for (int it = 0; it < 2; ++it) {
            int idx = tid * 2 + it;          // 0..511 float4 slots
            int row = idx >> 2;
            int cf = idx & 3;
            int gr = m0 + row;
            stA[it] = make_float4(0.f, 0.f, 0.f, 0.f);
            if (gr < NN) stA[it] = *(const float4*)(Asrc + (size_t)gr * DD + cf * 4);
        }
        #pragma unroll
        for (int it = 0; it < BLD; ++it) {
            int idx = tid + it * 256;        // float4 index into [16][BN]
            stB[it] = *(const float4*)(Wt + (size_t)kg * BN + idx * 4);
        }
    };
    auto storeT = [&](int buf) {
        #pragma unroll
        for (int it = 0; it < 2; ++it) {
            int idx = tid * 2 + it;
            int row = idx >> 2;
            int cf = idx & 3;
            As[buf][cf * 4 + 0][row] = stA[it].x;
            As[buf][cf * 4 + 1][row] = stA[it].y;
            As[buf][cf * 4 + 2][row] = stA[it].z;
            As[buf][cf * 4 + 3][row] = stA[it].w;
        }
        #pragma unroll
        for (int it = 0; it < BLD; ++it) {
            int idx = tid + it * 256;
            *(float4*)(&Bs[buf][0][0] + idx * 4) = stB[it];
        }
    };

    // prologue: tile 0
    loadT(0);
    storeT(0);
    __syncthreads();

    #pragma unroll 1
    for (int kt = 0; kt < 16; ++kt) {
        const int buf = kt & 1;
        if (kt < 15) loadT(kt + 1);     // prefetch overlaps compute below
        #pragma unroll
        for (int k = 0; k < 16; ++k) {
            float4 a0 = *(const float4*)&As[buf][k][ty * 8];
            float4 a1 = *(const float4*)&As[buf][k][ty * 8 + 4];
            float a[8] = {a0.x, a0.y, a0.z, a0.w, a1.x, a1.y, a1.z, a1.w};
            ull a2[8];
            #pragma unroll
            for (int i = 0; i < 8; ++i) a2[i] = pack2(a[i], a[i]);
            ull b2[2][NP];
            #pragma unroll
            for (int g = 0; g < 2; ++g) {
                const float2* bp = (const float2*)&Bs[buf][k][g * (BN / 2) + tx * G];
                #pragma unroll
                for (int p = 0; p < NP; ++p) {
                    float2 t = bp[p];
                    b2[g][p] = pack2(t.x, t.y);
                }
            }
            #pragma unroll
            for (int i = 0; i < 8; ++i)
                #pragma unroll
                for (int g = 0; g < 2; ++g)
                    #pragma unroll
                    for (int p = 0; p < NP; ++p)
                        fma2(acc[i][g][p], a2[i], b2[g][p]);
        }
        if (kt < 15) {
            storeT(buf ^ 1);
            __syncthreads();
        }
    }

    // bias (per-group pairs)
    float2 bv[2][NP];
    #pragma unroll
    for (int g = 0; g < 2; ++g)
        #pragma unroll
        for (int p = 0; p < NP; ++p) {
            int c = g * (BN / 2) + tx * G + p * 2;
            bv[g][p] = make_float2(__ldg(&bias[c]), __ldg(&bias[c + 1]));
        }

    #pragma unroll
    for (int i = 0; i < 8; ++i) {
        int r = m0 + ty * 8 + i;
        if (r < NN) {
            #pragma unroll
            for (int g = 0; g < 2; ++g) {
                float vals[G];
                #pragma unroll
                for (int p = 0; p < NP; ++p) {
                    float2 t = unpack2(acc[i][g][p]);
                    float v0 = t.x + bv[g][p].x;
                    float v1 = t.y + bv[g][p].y;
                    if (RELU) { v0 = fmaxf(v0, 0.f); v1 = fmaxf(v1, 0.f); }
                    vals[p * 2] = v0; vals[p * 2 + 1] = v1;
                }
                float* op = out + (size_t)r * BN + g * (BN / 2) + tx * G;
                if (G == 4) {
                    *(float4*)op = make_float4(vals[0], vals[1], vals[G > 2 ? 2 : 0], vals[G > 2 ? 3 : 1]);
                } else {
                    *(float2*)op = make_float2(vals[0], vals[1]);
                }
            }
        }
    }
}

// ---------------- launch ----------------
extern "C" void kernel_launch(void* const* d_in, const int* in_sizes, int n_in,
                              void* d_out, int out_size) {
    (void)in_sizes; (void)n_in; (void)out_size;
    const float* x  = (const float*)d_in[0];
    const int*   ei = (const int*)d_in[1];
    const float* ew = (const float*)d_in[2];
    const float* W0 = (const float*)d_in[3];
    const float* b0 = (const float*)d_in[4];
    const float* W1 = (const float*)d_in[5];
    const float* b1 = (const float*)d_in[6];
    const float* W2 = (const float*)d_in[7];
    const float* b2 = (const float*)d_in[8];
    float* out = (float*)d_out;

    void *p_cnt, *p_deg, *p_h0, *p_h1, *p_w0, *p_w1, *p_w2;
    cudaGetSymbolAddress(&p_cnt, g_cnt);
    cudaGetSymbolAddress(&p_deg, g_deg);
    cudaGetSymbolAddress(&p_h0,  g_h0);
    cudaGetSymbolAddress(&p_h1,  g_h1);
    cudaGetSymbolAddress(&p_w0,  g_Wt0);
    cudaGetSymbolAddress(&p_w1,  g_Wt1);
    cudaGetSymbolAddress(&p_w2,  g_Wt2);
    float* h0 = (float*)p_h0;
    float* h1 = (float*)p_h1;

    cudaMemsetAsync(p_cnt, 0, NN * sizeof(int), 0);
    cudaMemsetAsync(p_deg, 0, NN * sizeof(float), 0);

    const int totW = 2 * KK * 128 + KK * 64;
    transpose_W<<<(totW + 255) / 256, 256>>>(W0, W1, W2);
    count_kernel<<<(NE + 255) / 256, 256>>>(ei, ew);
    scan_kernel<<<1, 1024>>>();
    fill_kernel<<<(NE + 255) / 256, 256>>>(ei, ew);

    const int aggBlocks  = (NN + 7) / 8;          // 8 warps/block of 256
    const int gemmBlocks = (NN + 127) / 128;

    // layer 0: h0 = relu([x | agg(x)] @ W0^T + b0)
    agg_kernel<<<aggBlocks, 256>>>(x);
    gemm_kernel<128, 8, true><<<gemmBlocks, 256>>>(x, (const float*)p_w0, b0, h0);

    // layer 1: h1 = relu([h0 | agg(h0)] @ W1^T + b1)
    agg_kernel<<<aggBlocks, 256>>>(h0);
    gemm_kernel<128, 8, true><<<gemmBlocks, 256>>>(h0, (const float*)p_w1, b1, h1);

    // layer 2: out = [h1 | agg(h1)] @ W2^T + b2
    agg_kernel<<<aggBlocks, 256>>>(h1);
    gemm_kernel<64, 4, false><<<gemmBlocks, 256>>>(h1, (const float*)p_w2, b2, out);
}